// round 11
// baseline (speedup 1.0000x reference)
#include <cuda_runtime.h>
#include <cuda_bf16.h>
#include <cstdint>

// Problem constants
#define KW 7
#define CC 256
#define BB 4
#define HWN 1024          // 32*32
#define PW2 40            // padded smem row stride (floats)
#define PHW2 (38 * PW2)   // 1520 floats per plane

// Scratch (device globals)
__device__ float g_q[BB * CC * HWN];
__device__ float g_k[BB * CC * HWN];
__device__ float g_v[BB * CC * HWN];
__device__ __nv_bfloat16 g_Whi[3 * 256 * 256];
__device__ __nv_bfloat16 g_Wlo[3 * 256 * 256];
__device__ __nv_bfloat16 g_Xhi[BB * 256 * 1024];
__device__ __nv_bfloat16 g_Xlo[BB * 256 * 1024];
// [0]=gemm tile ctr, [1]=attn plane ctr, [2..5]=done[b], [6,7]=pad
__device__ int g_ctrs[8];

// ---------------------------------------------------------------------------
// helpers
// ---------------------------------------------------------------------------
__device__ __forceinline__ uint32_t smem_u32(const void* p) {
    uint32_t a;
    asm("{ .reg .u64 t; cvta.to.shared.u64 t, %1; cvt.u32.u64 %0, t; }" : "=r"(a) : "l"(p));
    return a;
}
__device__ __forceinline__ void ldsm_x4(uint32_t r[4], uint32_t addr) {
    asm volatile("ldmatrix.sync.aligned.m8n8.x4.shared.b16 {%0,%1,%2,%3}, [%4];"
                 : "=r"(r[0]), "=r"(r[1]), "=r"(r[2]), "=r"(r[3]) : "r"(addr));
}
__device__ __forceinline__ void ldsm_x4_t(uint32_t r[4], uint32_t addr) {
    asm volatile("ldmatrix.sync.aligned.m8n8.x4.trans.shared.b16 {%0,%1,%2,%3}, [%4];"
                 : "=r"(r[0]), "=r"(r[1]), "=r"(r[2]), "=r"(r[3]) : "r"(addr));
}
__device__ __forceinline__ void mma_bf16(float c[4], const uint32_t a[4],
                                         uint32_t b0, uint32_t b1) {
    asm volatile(
        "mma.sync.aligned.m16n8k16.row.col.f32.bf16.bf16.f32 "
        "{%0,%1,%2,%3}, {%4,%5,%6,%7}, {%8,%9}, {%0,%1,%2,%3};"
        : "+f"(c[0]), "+f"(c[1]), "+f"(c[2]), "+f"(c[3])
        : "r"(a[0]), "r"(a[1]), "r"(a[2]), "r"(a[3]), "r"(b0), "r"(b1));
}
__device__ __forceinline__ void split_bf(float a, __nv_bfloat16& h, __nv_bfloat16& l) {
    h = __float2bfloat16(a);
    l = __float2bfloat16(a - __bfloat162float(h));
}
__device__ __forceinline__ uint32_t pack2(__nv_bfloat16 a, __nv_bfloat16 b) {
    __nv_bfloat162 t; t.x = a; t.y = b;
    return *(uint32_t*)&t;
}
#define CP_ASYNC16(dst, src) \
    asm volatile("cp.async.cg.shared.global [%0], [%1], 16;" :: "r"(dst), "l"(src))
#define CP_COMMIT() asm volatile("cp.async.commit_group;" ::: "memory")
#define CP_WAIT(N)  asm volatile("cp.async.wait_group %0;" :: "n"(N) : "memory")

__device__ __forceinline__ float ex2f(float x) {
    float y;
    asm("ex2.approx.ftz.f32 %0, %1;" : "=f"(y) : "f"(x));
    return y;
}

// ---------------------------------------------------------------------------
// Pre-convert: grid 1216 x 256, 1 float4/thread. Resets work counters.
// ---------------------------------------------------------------------------
__global__ __launch_bounds__(256) void convert_kernel(
    const float* __restrict__ x,
    const float* __restrict__ wq,
    const float* __restrict__ wk,
    const float* __restrict__ wv)
{
    const int tid = threadIdx.x;
    if (blockIdx.x == 0 && tid < 8) g_ctrs[tid] = 0;

    __nv_bfloat16 h0, l0, h1, l1, h2, l2, h3, l3;
    if (blockIdx.x < 1024) {
        int i4 = blockIdx.x * 256 + tid;
        float4 v = ((const float4*)x)[i4];
        split_bf(v.x, h0, l0); split_bf(v.y, h1, l1);
        split_bf(v.z, h2, l2); split_bf(v.w, h3, l3);
        int base = i4 * 4;
        *(uint2*)&g_Xhi[base] = make_uint2(pack2(h0, h1), pack2(h2, h3));
        *(uint2*)&g_Xlo[base] = make_uint2(pack2(l0, l1), pack2(l2, l3));
    } else {
        int i4 = (blockIdx.x - 1024) * 256 + tid;
        int mat = i4 >> 14;
        int off4 = i4 & 16383;
        const float* Wp = (mat == 0) ? wq : (mat == 1) ? wk : wv;
        float4 v = ((const float4*)Wp)[off4];
        split_bf(v.x, h0, l0); split_bf(v.y, h1, l1);
        split_bf(v.z, h2, l2); split_bf(v.w, h3, l3);
        int base = i4 * 4;
        *(uint2*)&g_Whi[base] = make_uint2(pack2(h0, h1), pack2(h2, h3));
        *(uint2*)&g_Wlo[base] = make_uint2(pack2(l0, l1), pack2(l2, l3));
    }
}

// ---------------------------------------------------------------------------
// Fused GEMM + attention.
// grid 444 (=3x148, all resident @ 59KB smem).
//  - CTAs [0,148): GEMM role, steal 64x128 tiles (384, batch-major),
//    signal done[b] after fence. Then fall through to attn.
//  - CTAs [148,444): attn immediately, plane-stealing gated on done[batch].
// ---------------------------------------------------------------------------
#define SKA 48
#define SKB 136
#define OFF_AL 6144
#define OFF_BH 12288
#define OFF_BL 20992
#define STG_BYTES 29696
#define SMEM_TOTAL (2 * STG_BYTES)

__global__ __launch_bounds__(256, 3) void fused_kernel(
    const float* __restrict__ rel_h,
    const float* __restrict__ rel_w,
    float* __restrict__ out)
{
    extern __shared__ char sm[];
    __shared__ int s_work;
    __shared__ float brow_s[8];
    const int tid = threadIdx.x;
    const uint32_t sm_base = smem_u32(sm);

    if (blockIdx.x < 148) {
        // ================= GEMM role =================
        const int wid  = tid >> 5;
        const int lane = tid & 31;
        const int wm   = wid >> 2;
        const int wn   = wid & 3;
        const int ar  = tid >> 2;
        const int ac  = (tid & 3) << 3;
        const int br  = tid >> 4;
        const int bc  = (tid & 15) << 3;
        const uint32_t adst = (uint32_t)(ar * SKA + ac) * 2u;
        const uint32_t bdst = (uint32_t)(br * SKB + bc) * 2u;

        for (;;) {
            if (tid == 0) s_work = atomicAdd(&g_ctrs[0], 1);
            __syncthreads();
            const int t = s_work;
            if (t >= 384) break;
            const int b   = t / 96;          // batch-major tile order
            const int tl  = t % 96;
            const int m0g = (tl >> 3) * 64;
            const int n0  = (tl & 7) * 128;

            const __nv_bfloat16* AgH = g_Whi + (size_t)(m0g + ar) * 256 + ac;
            const __nv_bfloat16* AgL = g_Wlo + (size_t)(m0g + ar) * 256 + ac;
            const __nv_bfloat16* BgH = g_Xhi + ((size_t)(b * 256 + br)) * 1024 + n0 + bc;
            const __nv_bfloat16* BgL = g_Xlo + ((size_t)(b * 256 + br)) * 1024 + n0 + bc;

            auto issue = [&](int ch) {
                const uint32_t stb = sm_base + (ch & 1) * STG_BYTES;
                const int k0 = ch * 32;
                CP_ASYNC16(stb + adst,          AgH + k0);
                CP_ASYNC16(stb + OFF_AL + adst, AgL + k0);
                #pragma unroll
                for (int tt = 0; tt < 2; tt++) {
                    uint32_t d = bdst + (uint32_t)(tt * 16 * SKB) * 2u;
                    CP_ASYNC16(stb + OFF_BH + d, BgH + (size_t)(k0 + tt * 16) * 1024);
                    CP_ASYNC16(stb + OFF_BL + d, BgL + (size_t)(k0 + tt * 16) * 1024);
                }
                CP_COMMIT();
            };

            issue(0);
            issue(1);

            float acc[2][4][4];
            #pragma unroll
            for (int i = 0; i < 2; i++)
                #pragma unroll
                for (int j = 0; j < 4; j++)
                    #pragma unroll
                    for (int r = 0; r < 4; r++) acc[i][j][r] = 0.f;

            #pragma unroll
            for (int ch = 0; ch < 8; ch++) {
                if (ch < 7) { CP_WAIT(1); } else { CP_WAIT(0); }
                __syncthreads();

                const uint32_t stb = sm_base + (ch & 1) * STG_BYTES;
                #pragma unroll
                for (int ks = 0; ks < 2; ks++) {
                    const int kk = ks * 16;
                    uint32_t afh[2][4], afl[2][4];
                    #pragma unroll
                    for (int mt = 0; mt < 2; mt++) {
                        uint32_t aoff = (uint32_t)((wm * 32 + mt * 16 + (lane & 15)) * SKA
                                                   + kk + ((lane >> 4) << 3)) * 2u;
                        ldsm_x4(afh[mt], stb + aoff);
                        ldsm_x4(afl[mt], stb + OFF_AL + aoff);
                    }
                    uint32_t bfh[4][2], bfl[4][2];
                    #pragma unroll
                    for (int pp = 0; pp < 2; pp++) {
                        uint32_t boff = (uint32_t)((kk + (lane & 15)) * SKB
                                                   + wn * 32 + pp * 16 + ((lane >> 4) << 3)) * 2u;
                        uint32_t r[4];
                        ldsm_x4_t(r, stb + OFF_BH + boff);
                        bfh[pp * 2][0] = r[0]; bfh[pp * 2][1] = r[1];
                        bfh[pp * 2 + 1][0] = r[2]; bfh[pp * 2 + 1][1] = r[3];
                        ldsm_x4_t(r, stb + OFF_BL + boff);
                        bfl[pp * 2][0] = r[0]; bfl[pp * 2][1] = r[1];
                        bfl[pp * 2 + 1][0] = r[2]; bfl[pp * 2 + 1][1] = r[3];
                    }
                    #pragma unroll
                    for (int mt = 0; mt < 2; mt++)
                        #pragma unroll
                        for (int nt = 0; nt < 4; nt++) {
                            mma_bf16(acc[mt][nt], afh[mt], bfh[nt][0], bfh[nt][1]);
                            mma_bf16(acc[mt][nt], afh[mt], bfl[nt][0], bfl[nt][1]);
                            mma_bf16(acc[mt][nt], afl[mt], bfh[nt][0], bfh[nt][1]);
                        }
                }
                __syncthreads();
                if (ch + 2 < 8) issue(ch + 2);
            }

            const int mat = m0g >> 8;
            float* outp = (mat == 0) ? g_q : (mat == 1) ? g_k : g_v;
            const int orow = (m0g & 255) + wm * 32;
            #pragma unroll
            for (int mt = 0; mt < 2; mt++) {
                int o = orow + mt * 16 + (lane >> 2);
                #pragma unroll
                for (int nt = 0; nt < 4; nt++) {
                    int n = n0 + wn * 32 + nt * 8 + ((lane & 3) << 1);
                    float* og = outp + ((size_t)(b * CC + o)) * HWN + n;
                    *(float2*)og = make_float2(acc[mt][nt][0], acc[mt][nt][1]);
                    *(float2*)(og + 8 * HWN) = make_float2(acc[mt][nt][2], acc[mt][nt][3]);
                }
            }
            __threadfence();          // each thread's stores visible device-wide
            __syncthreads();          // all threads fenced
            if (tid == 0) atomicAdd(&g_ctrs[2 + b], 1);
        }
    }

    // ================= attention phase (all CTAs) =================
    float* ks = (float*)sm;
    float* vs = ks + PHW2;
    const int p0 = tid * 4;
    const int h  = p0 >> 5;
    const int w0 = p0 & 31;
    const int pi0 = (h + 3) * PW2 + (w0 + 4);

    __syncthreads();     // GEMM smem use fully done before reuse
    {
        const float4 z = make_float4(0.f, 0.f, 0.f, 0.f);
        for (int i = tid; i < PHW2 / 4; i += 256) {
            ((float4*)ks)[i] = z;
            ((float4*)vs)[i] = z;
        }
    }

    const uint32_t ksa = smem_u32(ks) + pi0 * 4;
    const uint32_t vsa = smem_u32(vs) + pi0 * 4;
    const float LOG2E = 1.4426950408889634f;

    for (;;) {
        __syncthreads();                 // prior compute (and zeroing) done
        if (tid == 0) s_work = atomicAdd(&g_ctrs[1], 1);
        __syncthreads();
        const int p = s_work;
        if (p >= BB * CC) break;

        const int c = p & 255;
        const bool hsel = (c < CC / 2);
        const int bb = p >> 8;

        if (tid == 0) {
            volatile int* dc = &g_ctrs[2 + bb];
            while (*dc < 96) __nanosleep(256);
        }
        if (tid < KW)
            brow_s[tid] = hsel ? rel_h[c * KW + tid] : rel_w[(c - CC / 2) * KW + tid];
        __syncthreads();                 // spin satisfied + brow ready

        CP_ASYNC16(ksa, g_k + ((size_t)p) * HWN + p0);   // .cg -> L2, coherent
        CP_ASYNC16(vsa, g_v + ((size_t)p) * HWN + p0);
        CP_COMMIT();

        float4 qv = __ldcg((const float4*)(g_q + ((size_t)p) * HWN + p0));

        CP_WAIT(0);
        __syncthreads();

        float q2[4] = { qv.x * LOG2E, qv.y * LOG2E, qv.z * LOG2E, qv.w * LOG2E };
        float acc[4] = {0.f, 0.f, 0.f, 0.f};
        float sum[4] = {0.f, 0.f, 0.f, 0.f};

        if (hsel) {
            #pragma unroll
            for (int u = 0; u < KW; u++) {
                const int rbase = (h + u) * PW2 + w0 + 1;
                float kr[10], vr[10];
                #pragma unroll
                for (int i = 0; i < 10; i++) { kr[i] = ks[rbase + i]; vr[i] = vs[rbase + i]; }
                const float bu = brow_s[u];
                float qbu[4];
                #pragma unroll
                for (int jj = 0; jj < 4; jj++) qbu[jj] = q2[jj] * bu;
                #pragma unroll
                for (int v = 0; v < KW; v++) {
                    #pragma unroll
                    for (int jj = 0; jj < 4; jj++) {
                        float t = fmaf(q2[jj], kr[v + jj], qbu[jj]);
                        float e = ex2f(t);
                        sum[jj] += e;
                        acc[jj]  = fmaf(e, vr[v + jj], acc[jj]);
                    }
                }
            }
        } else {
            float qb[4][KW];
            #pragma unroll
            for (int jj = 0; jj < 4; jj++)
                #pragma unroll
                for (int i = 0; i < KW; i++)
                    qb[jj][i] = q2[jj] * brow_s[i];
            #pragma unroll
            for (int u = 0; u < KW; u++) {
                const int rbase = (h + u) * PW2 + w0 + 1;
                float kr[10], vr[10];
                #pragma unroll
                for (int i = 0; i < 10; i++) { kr[i] = ks[rbase + i]; vr[i] = vs[rbase + i]; }
                #pragma unroll
                for (int v = 0; v < KW; v++) {
                    #pragma unroll
                    for (int jj = 0; jj < 4; jj++) {
                        float t = fmaf(q2[jj], kr[v + jj], qb[jj][v]);
                        float e = ex2f(t);
                        sum[jj] += e;
                        acc[jj]  = fmaf(e, vr[v + jj], acc[jj]);
                    }
                }
            }
        }

        float* og = out + ((size_t)p) * HWN + p0;
        float4 r;
        r.x = __fdividef(acc[0], sum[0]);
        r.y = __fdividef(acc[1], sum[1]);
        r.z = __fdividef(acc[2], sum[2]);
        r.w = __fdividef(acc[3], sum[3]);
        *(float4*)og = r;
    }
}

// ---------------------------------------------------------------------------
extern "C" void kernel_launch(void* const* d_in, const int* in_sizes, int n_in,
                              void* d_out, int out_size)
{
    const float* x     = (const float*)d_in[0];
    const float* wq    = (const float*)d_in[1];
    const float* wk    = (const float*)d_in[2];
    const float* wv    = (const float*)d_in[3];
    const float* rel_h = (const float*)d_in[4];
    const float* rel_w = (const float*)d_in[5];
    float* out = (float*)d_out;

    cudaFuncSetAttribute(fused_kernel, cudaFuncAttributeMaxDynamicSharedMemorySize,
                         SMEM_TOTAL);

    convert_kernel<<<1216, 256>>>(x, wq, wk, wv);
    fused_kernel<<<444, 256, SMEM_TOTAL>>>(rel_h, rel_w, out);
}

// round 12
// speedup vs baseline: 1.0858x; 1.0858x over previous
#include <cuda_runtime.h>
#include <cuda_bf16.h>
#include <cstdint>

// Problem constants
#define KW 7
#define CC 256
#define BB 4
#define HWN 1024          // 32*32
#define PW2 41            // padded smem row stride (floats), odd -> conflict-free
#define PHW2 (38 * PW2)   // 1558 floats per plane

// Scratch (device globals)
__device__ float g_q[BB * CC * HWN];
__device__ float g_k[BB * CC * HWN];
__device__ float g_v[BB * CC * HWN];
__device__ __nv_bfloat16 g_Whi[3 * 256 * 256];
__device__ __nv_bfloat16 g_Wlo[3 * 256 * 256];
__device__ __nv_bfloat16 g_Xhi[BB * 256 * 1024];
__device__ __nv_bfloat16 g_Xlo[BB * 256 * 1024];
__device__ int g_attn_ctr;

// ---------------------------------------------------------------------------
// helpers
// ---------------------------------------------------------------------------
__device__ __forceinline__ uint32_t smem_u32(const void* p) {
    uint32_t a;
    asm("{ .reg .u64 t; cvta.to.shared.u64 t, %1; cvt.u32.u64 %0, t; }" : "=r"(a) : "l"(p));
    return a;
}
__device__ __forceinline__ void ldsm_x4(uint32_t r[4], uint32_t addr) {
    asm volatile("ldmatrix.sync.aligned.m8n8.x4.shared.b16 {%0,%1,%2,%3}, [%4];"
                 : "=r"(r[0]), "=r"(r[1]), "=r"(r[2]), "=r"(r[3]) : "r"(addr));
}
__device__ __forceinline__ void ldsm_x4_t(uint32_t r[4], uint32_t addr) {
    asm volatile("ldmatrix.sync.aligned.m8n8.x4.trans.shared.b16 {%0,%1,%2,%3}, [%4];"
                 : "=r"(r[0]), "=r"(r[1]), "=r"(r[2]), "=r"(r[3]) : "r"(addr));
}
__device__ __forceinline__ void mma_bf16(float c[4], const uint32_t a[4],
                                         uint32_t b0, uint32_t b1) {
    asm volatile(
        "mma.sync.aligned.m16n8k16.row.col.f32.bf16.bf16.f32 "
        "{%0,%1,%2,%3}, {%4,%5,%6,%7}, {%8,%9}, {%0,%1,%2,%3};"
        : "+f"(c[0]), "+f"(c[1]), "+f"(c[2]), "+f"(c[3])
        : "r"(a[0]), "r"(a[1]), "r"(a[2]), "r"(a[3]), "r"(b0), "r"(b1));
}
__device__ __forceinline__ void split_bf(float a, __nv_bfloat16& h, __nv_bfloat16& l) {
    h = __float2bfloat16(a);
    l = __float2bfloat16(a - __bfloat162float(h));
}
__device__ __forceinline__ uint32_t pack2(__nv_bfloat16 a, __nv_bfloat16 b) {
    __nv_bfloat162 t; t.x = a; t.y = b;
    return *(uint32_t*)&t;
}
#define CP_ASYNC16(dst, src) \
    asm volatile("cp.async.cg.shared.global [%0], [%1], 16;" :: "r"(dst), "l"(src))
#define CP_COMMIT() asm volatile("cp.async.commit_group;" ::: "memory")
#define CP_WAIT(N)  asm volatile("cp.async.wait_group %0;" :: "n"(N) : "memory")

__device__ __forceinline__ float ex2f(float x) {
    float y;
    asm("ex2.approx.ftz.f32 %0, %1;" : "=f"(y) : "f"(x));
    return y;
}

// ---------------------------------------------------------------------------
// Pre-convert: grid 1216 x 256, 1 float4/thread. Resets the attn counter.
// ---------------------------------------------------------------------------
__global__ __launch_bounds__(256) void convert_kernel(
    const float* __restrict__ x,
    const float* __restrict__ wq,
    const float* __restrict__ wk,
    const float* __restrict__ wv)
{
    const int tid = threadIdx.x;
    if (blockIdx.x == 0 && tid == 0) g_attn_ctr = 0;

    __nv_bfloat16 h0, l0, h1, l1, h2, l2, h3, l3;
    if (blockIdx.x < 1024) {
        int i4 = blockIdx.x * 256 + tid;
        float4 v = ((const float4*)x)[i4];
        split_bf(v.x, h0, l0); split_bf(v.y, h1, l1);
        split_bf(v.z, h2, l2); split_bf(v.w, h3, l3);
        int base = i4 * 4;
        *(uint2*)&g_Xhi[base] = make_uint2(pack2(h0, h1), pack2(h2, h3));
        *(uint2*)&g_Xlo[base] = make_uint2(pack2(l0, l1), pack2(l2, l3));
    } else {
        int i4 = (blockIdx.x - 1024) * 256 + tid;
        int mat = i4 >> 14;
        int off4 = i4 & 16383;
        const float* Wp = (mat == 0) ? wq : (mat == 1) ? wk : wv;
        float4 v = ((const float4*)Wp)[off4];
        split_bf(v.x, h0, l0); split_bf(v.y, h1, l1);
        split_bf(v.z, h2, l2); split_bf(v.w, h3, l3);
        int base = i4 * 4;
        *(uint2*)&g_Whi[base] = make_uint2(pack2(h0, h1), pack2(h2, h3));
        *(uint2*)&g_Wlo[base] = make_uint2(pack2(l0, l1), pack2(l2, l3));
    }
}

// ---------------------------------------------------------------------------
// bf16 split-precision QKV GEMM, cp.async 2-stage pipeline (3 CTAs/SM).
// 64x128 tile, BK=32, 8 warps. grid: x = 96, y = batch(4).
// ---------------------------------------------------------------------------
#define SKA 48
#define SKB 136
#define OFF_AL 6144
#define OFF_BH 12288
#define OFF_BL 20992
#define STG_BYTES 29696
#define SMEM_TOTAL (2 * STG_BYTES)

__global__ __launch_bounds__(256, 3) void qkv_mma_kernel()
{
    extern __shared__ char sm[];
    const uint32_t sm_base = smem_u32(sm);

    const int tid  = threadIdx.x;
    const int wid  = tid >> 5;
    const int lane = tid & 31;
    const int wm   = wid >> 2;
    const int wn   = wid & 3;
    const int b    = blockIdx.y;
    const int m0g  = (blockIdx.x >> 3) * 64;
    const int n0   = (blockIdx.x & 7) * 128;

    const int ar  = tid >> 2;
    const int ac  = (tid & 3) << 3;
    const int br  = tid >> 4;
    const int bc  = (tid & 15) << 3;

    const __nv_bfloat16* AgH = g_Whi + (size_t)(m0g + ar) * 256 + ac;
    const __nv_bfloat16* AgL = g_Wlo + (size_t)(m0g + ar) * 256 + ac;
    const __nv_bfloat16* BgH = g_Xhi + ((size_t)(b * 256 + br)) * 1024 + n0 + bc;
    const __nv_bfloat16* BgL = g_Xlo + ((size_t)(b * 256 + br)) * 1024 + n0 + bc;

    const uint32_t adst = (uint32_t)(ar * SKA + ac) * 2u;
    const uint32_t bdst = (uint32_t)(br * SKB + bc) * 2u;

    auto issue = [&](int ch) {
        const uint32_t stb = sm_base + (ch & 1) * STG_BYTES;
        const int k0 = ch * 32;
        CP_ASYNC16(stb + adst,          AgH + k0);
        CP_ASYNC16(stb + OFF_AL + adst, AgL + k0);
        #pragma unroll
        for (int t = 0; t < 2; t++) {
            uint32_t d = bdst + (uint32_t)(t * 16 * SKB) * 2u;
            CP_ASYNC16(stb + OFF_BH + d, BgH + (size_t)(k0 + t * 16) * 1024);
            CP_ASYNC16(stb + OFF_BL + d, BgL + (size_t)(k0 + t * 16) * 1024);
        }
        CP_COMMIT();
    };

    issue(0);
    issue(1);

    float acc[2][4][4];
    #pragma unroll
    for (int i = 0; i < 2; i++)
        #pragma unroll
        for (int j = 0; j < 4; j++)
            #pragma unroll
            for (int r = 0; r < 4; r++) acc[i][j][r] = 0.f;

    #pragma unroll
    for (int ch = 0; ch < 8; ch++) {
        if (ch < 7) { CP_WAIT(1); } else { CP_WAIT(0); }
        __syncthreads();

        const uint32_t stb = sm_base + (ch & 1) * STG_BYTES;
        #pragma unroll
        for (int ks = 0; ks < 2; ks++) {
            const int kk = ks * 16;
            uint32_t afh[2][4], afl[2][4];
            #pragma unroll
            for (int mt = 0; mt < 2; mt++) {
                uint32_t aoff = (uint32_t)((wm * 32 + mt * 16 + (lane & 15)) * SKA
                                           + kk + ((lane >> 4) << 3)) * 2u;
                ldsm_x4(afh[mt], stb + aoff);
                ldsm_x4(afl[mt], stb + OFF_AL + aoff);
            }
            uint32_t bfh[4][2], bfl[4][2];
            #pragma unroll
            for (int p = 0; p < 2; p++) {
                uint32_t boff = (uint32_t)((kk + (lane & 15)) * SKB
                                           + wn * 32 + p * 16 + ((lane >> 4) << 3)) * 2u;
                uint32_t r[4];
                ldsm_x4_t(r, stb + OFF_BH + boff);
                bfh[p * 2][0] = r[0]; bfh[p * 2][1] = r[1];
                bfh[p * 2 + 1][0] = r[2]; bfh[p * 2 + 1][1] = r[3];
                ldsm_x4_t(r, stb + OFF_BL + boff);
                bfl[p * 2][0] = r[0]; bfl[p * 2][1] = r[1];
                bfl[p * 2 + 1][0] = r[2]; bfl[p * 2 + 1][1] = r[3];
            }
            #pragma unroll
            for (int mt = 0; mt < 2; mt++)
                #pragma unroll
                for (int nt = 0; nt < 4; nt++) {
                    mma_bf16(acc[mt][nt], afh[mt], bfh[nt][0], bfh[nt][1]);
                    mma_bf16(acc[mt][nt], afh[mt], bfl[nt][0], bfl[nt][1]);
                    mma_bf16(acc[mt][nt], afl[mt], bfh[nt][0], bfh[nt][1]);
                }
        }
        __syncthreads();
        if (ch + 2 < 8) issue(ch + 2);
    }

    const int mat = m0g >> 8;
    float* outp = (mat == 0) ? g_q : (mat == 1) ? g_k : g_v;
    const int orow = (m0g & 255) + wm * 32;
    #pragma unroll
    for (int mt = 0; mt < 2; mt++) {
        int o = orow + mt * 16 + (lane >> 2);
        #pragma unroll
        for (int nt = 0; nt < 4; nt++) {
            int n = n0 + wn * 32 + nt * 8 + ((lane & 3) << 1);
            float* og = outp + ((size_t)(b * CC + o)) * HWN + n;
            *(float2*)og = make_float2(acc[mt][nt][0], acc[mt][nt][1]);
            *(float2*)(og + 8 * HWN) = make_float2(acc[mt][nt][2], acc[mt][nt][3]);
        }
    }
}

// ---------------------------------------------------------------------------
// Windowed softmax attention: persistent blocks, conflict-free smem (stride 41).
// grid 592 (= 4 x 148); 1024 plane work-units.
// Pixel (hh,ww) stored at [(hh+3)*41 + ww+3]; window reads conflict-free
// because bank = (9h + 4t + c) mod 32 covers all 32 banks.
// ---------------------------------------------------------------------------
__global__ __launch_bounds__(256) void attn_kernel(
    const float* __restrict__ rel_h,
    const float* __restrict__ rel_w,
    float* __restrict__ out)
{
    __shared__ float ks[PHW2];
    __shared__ float vs[PHW2];
    __shared__ float brow_s[8];
    __shared__ int s_p;

    const int tid = threadIdx.x;
    const int p0 = tid * 4;
    const int h  = p0 >> 5;
    const int w0 = p0 & 31;
    const int pi0 = (h + 3) * PW2 + (w0 + 3);   // store slot for 4 pixels

    // zero once; borders stay zero, interior overwritten per plane
    for (int i = tid; i < PHW2; i += 256) { ks[i] = 0.f; vs[i] = 0.f; }

    const float LOG2E = 1.4426950408889634f;

    for (;;) {
        __syncthreads();                 // prior compute done (and zeroing, first pass)
        if (tid == 0) s_p = atomicAdd(&g_attn_ctr, 1);
        __syncthreads();
        const int p = s_p;
        if (p >= BB * CC) break;

        const int c = p & 255;
        const bool hsel = (c < CC / 2);

        if (tid < KW)
            brow_s[tid] = hsel ? rel_h[c * KW + tid] : rel_w[(c - CC / 2) * KW + tid];

        // fill k/v planes (conflict-free scalar STS)
        float4 k4 = __ldcg((const float4*)(g_k + ((size_t)p) * HWN + p0));
        float4 v4 = __ldcg((const float4*)(g_v + ((size_t)p) * HWN + p0));
        ks[pi0 + 0] = k4.x; ks[pi0 + 1] = k4.y; ks[pi0 + 2] = k4.z; ks[pi0 + 3] = k4.w;
        vs[pi0 + 0] = v4.x; vs[pi0 + 1] = v4.y; vs[pi0 + 2] = v4.z; vs[pi0 + 3] = v4.w;

        float4 qv = *(const float4*)(g_q + ((size_t)p) * HWN + p0);

        __syncthreads();

        float q2[4] = { qv.x * LOG2E, qv.y * LOG2E, qv.z * LOG2E, qv.w * LOG2E };
        float acc[4] = {0.f, 0.f, 0.f, 0.f};
        float sum[4] = {0.f, 0.f, 0.f, 0.f};

        if (hsel) {
            #pragma unroll
            for (int u = 0; u < KW; u++) {
                const int rbase = (h + u) * PW2 + w0;
                float kr[10], vr[10];
                #pragma unroll
                for (int i = 0; i < 10; i++) { kr[i] = ks[rbase + i]; vr[i] = vs[rbase + i]; }
                const float bu = brow_s[u];
                float qbu[4];
                #pragma unroll
                for (int jj = 0; jj < 4; jj++) qbu[jj] = q2[jj] * bu;
                #pragma unroll
                for (int v = 0; v < KW; v++) {
                    #pragma unroll
                    for (int jj = 0; jj < 4; jj++) {
                        float t = fmaf(q2[jj], kr[v + jj], qbu[jj]);
                        float e = ex2f(t);
                        sum[jj] += e;
                        acc[jj]  = fmaf(e, vr[v + jj], acc[jj]);
                    }
                }
            }
        } else {
            float qb[4][KW];
            #pragma unroll
            for (int jj = 0; jj < 4; jj++)
                #pragma unroll
                for (int i = 0; i < KW; i++)
                    qb[jj][i] = q2[jj] * brow_s[i];
            #pragma unroll
            for (int u = 0; u < KW; u++) {
                const int rbase = (h + u) * PW2 + w0;
                float kr[10], vr[10];
                #pragma unroll
                for (int i = 0; i < 10; i++) { kr[i] = ks[rbase + i]; vr[i] = vs[rbase + i]; }
                #pragma unroll
                for (int v = 0; v < KW; v++) {
                    #pragma unroll
                    for (int jj = 0; jj < 4; jj++) {
                        float t = fmaf(q2[jj], kr[v + jj], qb[jj][v]);
                        float e = ex2f(t);
                        sum[jj] += e;
                        acc[jj]  = fmaf(e, vr[v + jj], acc[jj]);
                    }
                }
            }
        }

        float* og = out + ((size_t)p) * HWN + p0;
        float4 r;
        r.x = __fdividef(acc[0], sum[0]);
        r.y = __fdividef(acc[1], sum[1]);
        r.z = __fdividef(acc[2], sum[2]);
        r.w = __fdividef(acc[3], sum[3]);
        *(float4*)og = r;
    }
}

// ---------------------------------------------------------------------------
extern "C" void kernel_launch(void* const* d_in, const int* in_sizes, int n_in,
                              void* d_out, int out_size)
{
    const float* x     = (const float*)d_in[0];
    const float* wq    = (const float*)d_in[1];
    const float* wk    = (const float*)d_in[2];
    const float* wv    = (const float*)d_in[3];
    const float* rel_h = (const float*)d_in[4];
    const float* rel_w = (const float*)d_in[5];
    float* out = (float*)d_out;

    cudaFuncSetAttribute(qkv_mma_kernel, cudaFuncAttributeMaxDynamicSharedMemorySize,
                         SMEM_TOTAL);

    convert_kernel<<<1216, 256>>>(x, wq, wk, wv);

    dim3 gg(96, BB);
    qkv_mma_kernel<<<gg, 256, SMEM_TOTAL>>>();

    attn_kernel<<<592, 256>>>(rel_h, rel_w, out);
}

// round 14
// speedup vs baseline: 1.0995x; 1.0125x over previous
#include <cuda_runtime.h>
#include <cuda_bf16.h>
#include <cstdint>

// Problem constants
#define KW 7
#define CC 256
#define BB 4
#define HWN 1024          // 32*32
#define PW2 40            // padded smem row stride (floats), mult of 4 -> aligned reads
#define PHW2 (38 * PW2)   // 1520 floats per plane

// Scratch (device globals)
__device__ float g_q[BB * CC * HWN];
__device__ float g_k[BB * CC * HWN];
__device__ float g_v[BB * CC * HWN];
__device__ __nv_bfloat16 g_Whi[3 * 256 * 256];
__device__ __nv_bfloat16 g_Wlo[3 * 256 * 256];
__device__ __nv_bfloat16 g_Xhi[BB * 256 * 1024];
__device__ __nv_bfloat16 g_Xlo[BB * 256 * 1024];
__device__ int g_attn_ctr;

// ---------------------------------------------------------------------------
// helpers
// ---------------------------------------------------------------------------
__device__ __forceinline__ uint32_t smem_u32(const void* p) {
    uint32_t a;
    asm("{ .reg .u64 t; cvta.to.shared.u64 t, %1; cvt.u32.u64 %0, t; }" : "=r"(a) : "l"(p));
    return a;
}
__device__ __forceinline__ void ldsm_x4(uint32_t r[4], uint32_t addr) {
    asm volatile("ldmatrix.sync.aligned.m8n8.x4.shared.b16 {%0,%1,%2,%3}, [%4];"
                 : "=r"(r[0]), "=r"(r[1]), "=r"(r[2]), "=r"(r[3]) : "r"(addr));
}
__device__ __forceinline__ void ldsm_x4_t(uint32_t r[4], uint32_t addr) {
    asm volatile("ldmatrix.sync.aligned.m8n8.x4.trans.shared.b16 {%0,%1,%2,%3}, [%4];"
                 : "=r"(r[0]), "=r"(r[1]), "=r"(r[2]), "=r"(r[3]) : "r"(addr));
}
__device__ __forceinline__ void mma_bf16(float c[4], const uint32_t a[4],
                                         uint32_t b0, uint32_t b1) {
    asm volatile(
        "mma.sync.aligned.m16n8k16.row.col.f32.bf16.bf16.f32 "
        "{%0,%1,%2,%3}, {%4,%5,%6,%7}, {%8,%9}, {%0,%1,%2,%3};"
        : "+f"(c[0]), "+f"(c[1]), "+f"(c[2]), "+f"(c[3])
        : "r"(a[0]), "r"(a[1]), "r"(a[2]), "r"(a[3]), "r"(b0), "r"(b1));
}
__device__ __forceinline__ void split_bf(float a, __nv_bfloat16& h, __nv_bfloat16& l) {
    h = __float2bfloat16(a);
    l = __float2bfloat16(a - __bfloat162float(h));
}
__device__ __forceinline__ uint32_t pack2(__nv_bfloat16 a, __nv_bfloat16 b) {
    __nv_bfloat162 t; t.x = a; t.y = b;
    return *(uint32_t*)&t;
}
#define CP_ASYNC16(dst, src) \
    asm volatile("cp.async.cg.shared.global [%0], [%1], 16;" :: "r"(dst), "l"(src))
#define CP_COMMIT() asm volatile("cp.async.commit_group;" ::: "memory")
#define CP_WAIT(N)  asm volatile("cp.async.wait_group %0;" :: "n"(N) : "memory")

__device__ __forceinline__ float ex2f(float x) {
    float y;
    asm("ex2.approx.ftz.f32 %0, %1;" : "=f"(y) : "f"(x));
    return y;
}

// ---------------------------------------------------------------------------
// Pre-convert: grid 1216 x 256, 1 float4/thread. Resets the attn counter.
// ---------------------------------------------------------------------------
__global__ __launch_bounds__(256) void convert_kernel(
    const float* __restrict__ x,
    const float* __restrict__ wq,
    const float* __restrict__ wk,
    const float* __restrict__ wv)
{
    const int tid = threadIdx.x;
    if (blockIdx.x == 0 && tid == 0) g_attn_ctr = 0;

    __nv_bfloat16 h0, l0, h1, l1, h2, l2, h3, l3;
    if (blockIdx.x < 1024) {
        int i4 = blockIdx.x * 256 + tid;
        float4 v = ((const float4*)x)[i4];
        split_bf(v.x, h0, l0); split_bf(v.y, h1, l1);
        split_bf(v.z, h2, l2); split_bf(v.w, h3, l3);
        int base = i4 * 4;
        *(uint2*)&g_Xhi[base] = make_uint2(pack2(h0, h1), pack2(h2, h3));
        *(uint2*)&g_Xlo[base] = make_uint2(pack2(l0, l1), pack2(l2, l3));
    } else {
        int i4 = (blockIdx.x - 1024) * 256 + tid;
        int mat = i4 >> 14;
        int off4 = i4 & 16383;
        const float* Wp = (mat == 0) ? wq : (mat == 1) ? wk : wv;
        float4 v = ((const float4*)Wp)[off4];
        split_bf(v.x, h0, l0); split_bf(v.y, h1, l1);
        split_bf(v.z, h2, l2); split_bf(v.w, h3, l3);
        int base = i4 * 4;
        *(uint2*)&g_Whi[base] = make_uint2(pack2(h0, h1), pack2(h2, h3));
        *(uint2*)&g_Wlo[base] = make_uint2(pack2(l0, l1), pack2(l2, l3));
    }
}

// ---------------------------------------------------------------------------
// bf16 split-precision QKV GEMM, cp.async 2-stage pipeline (3 CTAs/SM).
// 64x128 tile, BK=32, 8 warps. grid: x = 96, y = batch(4).
// ---------------------------------------------------------------------------
#define SKA 48
#define SKB 136
#define OFF_AL 6144
#define OFF_BH 12288
#define OFF_BL 20992
#define STG_BYTES 29696
#define SMEM_TOTAL (2 * STG_BYTES)

__global__ __launch_bounds__(256, 3) void qkv_mma_kernel()
{
    extern __shared__ char sm[];
    const uint32_t sm_base = smem_u32(sm);

    const int tid  = threadIdx.x;
    const int wid  = tid >> 5;
    const int lane = tid & 31;
    const int wm   = wid >> 2;
    const int wn   = wid & 3;
    const int b    = blockIdx.y;
    const int m0g  = (blockIdx.x >> 3) * 64;
    const int n0   = (blockIdx.x & 7) * 128;

    const int ar  = tid >> 2;
    const int ac  = (tid & 3) << 3;
    const int br  = tid >> 4;
    const int bc  = (tid & 15) << 3;

    const __nv_bfloat16* AgH = g_Whi + (size_t)(m0g + ar) * 256 + ac;
    const __nv_bfloat16* AgL = g_Wlo + (size_t)(m0g + ar) * 256 + ac;
    const __nv_bfloat16* BgH = g_Xhi + ((size_t)(b * 256 + br)) * 1024 + n0 + bc;
    const __nv_bfloat16* BgL = g_Xlo + ((size_t)(b * 256 + br)) * 1024 + n0 + bc;

    const uint32_t adst = (uint32_t)(ar * SKA + ac) * 2u;
    const uint32_t bdst = (uint32_t)(br * SKB + bc) * 2u;

    auto issue = [&](int ch) {
        const uint32_t stb = sm_base + (ch & 1) * STG_BYTES;
        const int k0 = ch * 32;
        CP_ASYNC16(stb + adst,          AgH + k0);
        CP_ASYNC16(stb + OFF_AL + adst, AgL + k0);
        #pragma unroll
        for (int t = 0; t < 2; t++) {
            uint32_t d = bdst + (uint32_t)(t * 16 * SKB) * 2u;
            CP_ASYNC16(stb + OFF_BH + d, BgH + (size_t)(k0 + t * 16) * 1024);
            CP_ASYNC16(stb + OFF_BL + d, BgL + (size_t)(k0 + t * 16) * 1024);
        }
        CP_COMMIT();
    };

    issue(0);
    issue(1);

    float acc[2][4][4];
    #pragma unroll
    for (int i = 0; i < 2; i++)
        #pragma unroll
        for (int j = 0; j < 4; j++)
            #pragma unroll
            for (int r = 0; r < 4; r++) acc[i][j][r] = 0.f;

    #pragma unroll
    for (int ch = 0; ch < 8; ch++) {
        if (ch < 7) { CP_WAIT(1); } else { CP_WAIT(0); }
        __syncthreads();

        const uint32_t stb = sm_base + (ch & 1) * STG_BYTES;
        #pragma unroll
        for (int ks = 0; ks < 2; ks++) {
            const int kk = ks * 16;
            uint32_t afh[2][4], afl[2][4];
            #pragma unroll
            for (int mt = 0; mt < 2; mt++) {
                uint32_t aoff = (uint32_t)((wm * 32 + mt * 16 + (lane & 15)) * SKA
                                           + kk + ((lane >> 4) << 3)) * 2u;
                ldsm_x4(afh[mt], stb + aoff);
                ldsm_x4(afl[mt], stb + OFF_AL + aoff);
            }
            uint32_t bfh[4][2], bfl[4][2];
            #pragma unroll
            for (int p = 0; p < 2; p++) {
                uint32_t boff = (uint32_t)((kk + (lane & 15)) * SKB
                                           + wn * 32 + p * 16 + ((lane >> 4) << 3)) * 2u;
                uint32_t r[4];
                ldsm_x4_t(r, stb + OFF_BH + boff);
                bfh[p * 2][0] = r[0]; bfh[p * 2][1] = r[1];
                bfh[p * 2 + 1][0] = r[2]; bfh[p * 2 + 1][1] = r[3];
                ldsm_x4_t(r, stb + OFF_BL + boff);
                bfl[p * 2][0] = r[0]; bfl[p * 2][1] = r[1];
                bfl[p * 2 + 1][0] = r[2]; bfl[p * 2 + 1][1] = r[3];
            }
            #pragma unroll
            for (int mt = 0; mt < 2; mt++)
                #pragma unroll
                for (int nt = 0; nt < 4; nt++) {
                    mma_bf16(acc[mt][nt], afh[mt], bfh[nt][0], bfh[nt][1]);
                    mma_bf16(acc[mt][nt], afh[mt], bfl[nt][0], bfl[nt][1]);
                    mma_bf16(acc[mt][nt], afl[mt], bfh[nt][0], bfh[nt][1]);
                }
        }
        __syncthreads();
        if (ch + 2 < 8) issue(ch + 2);
    }

    const int mat = m0g >> 8;
    float* outp = (mat == 0) ? g_q : (mat == 1) ? g_k : g_v;
    const int orow = (m0g & 255) + wm * 32;
    #pragma unroll
    for (int mt = 0; mt < 2; mt++) {
        int o = orow + mt * 16 + (lane >> 2);
        #pragma unroll
        for (int nt = 0; nt < 4; nt++) {
            int n = n0 + wn * 32 + nt * 8 + ((lane & 3) << 1);
            float* og = outp + ((size_t)(b * CC + o)) * HWN + n;
            *(float2*)og = make_float2(acc[mt][nt][0], acc[mt][nt][1]);
            *(float2*)(og + 8 * HWN) = make_float2(acc[mt][nt][2], acc[mt][nt][3]);
        }
    }
}

// ---------------------------------------------------------------------------
// Windowed softmax attention: persistent blocks, VECTORIZED smem reads.
// Stride 40, left-pad 3: pixel (hh,ww) at [(hh+3)*40 + ww+3]; window reads
// start at (h+u)*40 + w0 which is = 0 mod 4 -> LDS.128/LDS.64 legal for all u.
// LDS count per u: 20 scalar -> 6 vector (LSU-dispatch bound removed).
// grid 592 (= 4 x 148); 1024 plane work-units.
// ---------------------------------------------------------------------------
__global__ __launch_bounds__(256) void attn_kernel(
    const float* __restrict__ rel_h,
    const float* __restrict__ rel_w,
    float* __restrict__ out)
{
    __shared__ __align__(16) float ks[PHW2];
    __shared__ __align__(16) float vs[PHW2];
    __shared__ float brow_s[8];
    __shared__ int s_p;

    const int tid = threadIdx.x;
    const int p0 = tid * 4;
    const int h  = p0 >> 5;
    const int w0 = p0 & 31;
    const int pi0 = (h + 3) * PW2 + (w0 + 3);   // store slot (mod 4 == 3: scalar fill)

    // zero once; borders stay zero, interior overwritten per plane
    {
        const float4 z = make_float4(0.f, 0.f, 0.f, 0.f);
        for (int i = tid; i < PHW2 / 4; i += 256) {
            ((float4*)ks)[i] = z;
            ((float4*)vs)[i] = z;
        }
    }

    const float LOG2E = 1.4426950408889634f;

    for (;;) {
        __syncthreads();                 // prior compute done (and zeroing, first pass)
        if (tid == 0) s_p = atomicAdd(&g_attn_ctr, 1);
        __syncthreads();
        const int p = s_p;
        if (p >= BB * CC) break;

        const int c = p & 255;
        const bool hsel = (c < CC / 2);

        if (tid < KW)
            brow_s[tid] = hsel ? rel_h[c * KW + tid] : rel_w[(c - CC / 2) * KW + tid];

        // fill k/v planes (scalar STS; once per plane, cheap)
        float4 k4 = *(const float4*)(g_k + ((size_t)p) * HWN + p0);
        float4 v4 = *(const float4*)(g_v + ((size_t)p) * HWN + p0);
        ks[pi0 + 0] = k4.x; ks[pi0 + 1] = k4.y; ks[pi0 + 2] = k4.z; ks[pi0 + 3] = k4.w;
        vs[pi0 + 0] = v4.x; vs[pi0 + 1] = v4.y; vs[pi0 + 2] = v4.z; vs[pi0 + 3] = v4.w;

        float4 qv = *(const float4*)(g_q + ((size_t)p) * HWN + p0);

        __syncthreads();

        float q2[4] = { qv.x * LOG2E, qv.y * LOG2E, qv.z * LOG2E, qv.w * LOG2E };
        float acc[4] = {0.f, 0.f, 0.f, 0.f};
        float sum[4] = {0.f, 0.f, 0.f, 0.f};

        if (hsel) {
            #pragma unroll
            for (int u = 0; u < KW; u++) {
                const int rbase = (h + u) * PW2 + w0;     // == 0 mod 4
                float4 ka = *(const float4*)&ks[rbase];
                float4 kb = *(const float4*)&ks[rbase + 4];
                float2 kc = *(const float2*)&ks[rbase + 8];
                float4 va = *(const float4*)&vs[rbase];
                float4 vb = *(const float4*)&vs[rbase + 4];
                float2 vc = *(const float2*)&vs[rbase + 8];
                float kr[10] = { ka.x, ka.y, ka.z, ka.w, kb.x, kb.y, kb.z, kb.w, kc.x, kc.y };
                float vr[10] = { va.x, va.y, va.z, va.w, vb.x, vb.y, vb.z, vb.w, vc.x, vc.y };
                const float bu = brow_s[u];
                float qbu[4];
                #pragma unroll
                for (int jj = 0; jj < 4; jj++) qbu[jj] = q2[jj] * bu;
                #pragma unroll
                for (int v = 0; v < KW; v++) {
                    #pragma unroll
                    for (int jj = 0; jj < 4; jj++) {
                        float t = fmaf(q2[jj], kr[v + jj], qbu[jj]);
                        float e = ex2f(t);
                        sum[jj] += e;
                        acc[jj]  = fmaf(e, vr[v + jj], acc[jj]);
                    }
                }
            }
        } else {
            float qb[4][KW];
            #pragma unroll
            for (int jj = 0; jj < 4; jj++)
                #pragma unroll
                for (int i = 0; i < KW; i++)
                    qb[jj][i] = q2[jj] * brow_s[i];
            #pragma unroll
            for (int u = 0; u < KW; u++) {
                const int rbase = (h + u) * PW2 + w0;
                float4 ka = *(const float4*)&ks[rbase];
                float4 kb = *(const float4*)&ks[rbase + 4];
                float2 kc = *(const float2*)&ks[rbase + 8];
                float4 va = *(const float4*)&vs[rbase];
                float4 vb = *(const float4*)&vs[rbase + 4];
                float2 vc = *(const float2*)&vs[rbase + 8];
                float kr[10] = { ka.x, ka.y, ka.z, ka.w, kb.x, kb.y, kb.z, kb.w, kc.x, kc.y };
                float vr[10] = { va.x, va.y, va.z, va.w, vb.x, vb.y, vb.z, vb.w, vc.x, vc.y };
                #pragma unroll
                for (int v = 0; v < KW; v++) {
                    #pragma unroll
                    for (int jj = 0; jj < 4; jj++) {
                        float t = fmaf(q2[jj], kr[v + jj], qb[jj][v]);
                        float e = ex2f(t);
                        sum[jj] += e;
                        acc[jj]  = fmaf(e, vr[v + jj], acc[jj]);
                    }
                }
            }
        }

        float* og = out + ((size_t)p) * HWN + p0;
        float4 r;
        r.x = __fdividef(acc[0], sum[0]);
        r.y = __fdividef(acc[1], sum[1]);
        r.z = __fdividef(acc[2], sum[2]);
        r.w = __fdividef(acc[3], sum[3]);
        *(float4*)og = r;
    }
}

// ---------------------------------------------------------------------------
extern "C" void kernel_launch(void* const* d_in, const int* in_sizes, int n_in,
                              void* d_out, int out_size)
{
    const float* x     = (const float*)d_in[0];
    const float* wq    = (const float*)d_in[1];
    const float* wk    = (const float*)d_in[2];
    const float* wv    = (const float*)d_in[3];
    const float* rel_h = (const float*)d_in[4];
    const float* rel_w = (const float*)d_in[5];
    float* out = (float*)d_out;

    cudaFuncSetAttribute(qkv_mma_kernel, cudaFuncAttributeMaxDynamicSharedMemorySize,
                         SMEM_TOTAL);

    convert_kernel<<<1216, 256>>>(x, wq, wk, wv);

    dim3 gg(96, BB);
    qkv_mma_kernel<<<gg, 256, SMEM_TOTAL>>>();

    attn_kernel<<<592, 256>>>(rel_h, rel_w, out);
}